// round 2
// baseline (speedup 1.0000x reference)
#include <cuda_runtime.h>
#include <cuda_bf16.h>

// Problem: MultinomialCELoss
//   x: [N=8, Q=441, H=128, W=128] float32 (softmax probs)
//   y: [N=8, 2,    H=128, W=128] float32 (ab values in [-110,110))
//   out[w] = -sum_{n,h} log( x[n, idx(n,h,w), h, w] )
//   idx = clip(floor((y0+110)/10),0,20)*21 + clip(floor((y1+110)/10),0,20)
//
// R2: latency-bound fix — split n across blocks. grid=(128 h, 4 nchunk),
// 512 CTAs (~14 warps/SM resident) instead of 128 (~3.5 warps/SM).
// Each thread: 2 (y0,y1) pairs -> 2 scattered x gathers -> 2 logf -> 1 atomic.

#define N_  8
#define Q_  441
#define H_  128
#define W_  128
#define NBINS 21
#define NPB 2   // n-slices per block

__global__ void zero_out_kernel(float* out) {
    out[threadIdx.x] = 0.0f;
}

__device__ __forceinline__ int ab_bin(float v) {
    // Match JAX float32 semantics: floor((v + 110) / 10), clipped to [0,20].
    // __fdiv_rn keeps IEEE division even under fast-math (bin-boundary exactness).
    float q = floorf(__fdiv_rn(v + 110.0f, 10.0f));
    int qi = (int)q;
    qi = qi < 0 ? 0 : qi;
    qi = qi > (NBINS - 1) ? (NBINS - 1) : qi;
    return qi;
}

__global__ __launch_bounds__(W_) void mce_loss_kernel(
    const float* __restrict__ x,
    const float* __restrict__ y,
    float* __restrict__ out)
{
    const int w  = threadIdx.x;          // 0..127
    const int h  = blockIdx.x;           // 0..127
    const int n0 = blockIdx.y * NPB;     // 0,2,4,6
    const int hw = h * W_ + w;

    // Issue all y loads first (4 independent LDGs), then both gathers
    // back-to-back so the two 577-cycle DRAM chains overlap.
    int idx[NPB];
    #pragma unroll
    for (int i = 0; i < NPB; i++) {
        const int n = n0 + i;
        float ya = y[((size_t)n * 2 + 0) * (H_ * W_) + hw];
        float yb = y[((size_t)n * 2 + 1) * (H_ * W_) + hw];
        idx[i] = ab_bin(ya) * NBINS + ab_bin(yb);
    }

    float v[NPB];
    #pragma unroll
    for (int i = 0; i < NPB; i++) {
        const int n = n0 + i;
        v[i] = x[((size_t)n * Q_ + idx[i]) * (H_ * W_) + hw];
    }

    float acc = 0.0f;
    #pragma unroll
    for (int i = 0; i < NPB; i++) {
        acc += logf(v[i]);
    }

    // 512 atomics per out[w] address, 128 addresses spread over L2 slices —
    // well below the L2-atomic serialization knee.
    atomicAdd(&out[w], -acc);
}

extern "C" void kernel_launch(void* const* d_in, const int* in_sizes, int n_in,
                              void* d_out, int out_size) {
    const float* x = (const float*)d_in[0];
    const float* y = (const float*)d_in[1];
    float* out = (float*)d_out;

    zero_out_kernel<<<1, W_>>>(out);
    dim3 grid(H_, N_ / NPB);
    mce_loss_kernel<<<grid, W_>>>(x, y, out);
}